// round 5
// baseline (speedup 1.0000x reference)
#include <cuda_runtime.h>
#include <math.h>

#define D_ATOM 64
#define DOUT   128
#define DIN    192
#define BM     128
#define BK     16
#define MAX_E  1600000
#define MAX_N  50000

// ---- scratch (device globals: allocation-free contract) ----
__device__ float g_z[(size_t)MAX_E * DOUT];        // pre-BN GEMM output, 819MB
__device__ float g_upd[(size_t)MAX_N * D_ATOM];    // scatter-add accumulator
__device__ float g_stats1[2 * DOUT];               // sum / sumsq per BN1 column
__device__ float g_scale1[DOUT];
__device__ float g_shift1[DOUT];
__device__ float g_stats2[2 * D_ATOM];
__device__ float g_scale2[D_ATOM];
__device__ float g_shift2[D_ATOM];

__device__ __forceinline__ float softplus_f(float x) {
    // logaddexp(x, 0) = max(x,0) + log1p(exp(-|x|))
    return fmaxf(x, 0.f) + log1pf(expf(-fabsf(x)));
}

// ---- 0: zero accumulators (graph replays must be deterministic) ----
__global__ void init_kernel(int n_upd) {
    int i = blockIdx.x * blockDim.x + threadIdx.x;
    if (i < n_upd) g_upd[i] = 0.f;
    if (i < 2 * DOUT) g_stats1[i] = 0.f;
    if (i < 2 * D_ATOM) g_stats2[i] = 0.f;
}

// ---- 1: fused gather-concat GEMM + bias + BN1 statistics ----
// C[e, 0:128] = [atom[src[e]] | atom[dst[e]] | nbr[e]] @ W + b
// 128x128 tile per CTA, 256 threads, 8x8 microtile, K double-buffered in BK=16 chunks.
__global__ __launch_bounds__(256, 2)
void gemm_kernel(const float* __restrict__ atom, const float* __restrict__ nbr,
                 const int* __restrict__ esrc, const int* __restrict__ edst,
                 const float* __restrict__ W, const float* __restrict__ bias, int E)
{
    __shared__ __align__(16) float As[2][BM][BK + 4];   // +4 pad keeps float4 stores 16B-aligned, kills conflicts
    __shared__ __align__(16) float Ws[2][BK][DOUT];
    __shared__ int s_src[BM], s_dst[BM];
    __shared__ float s_sum[DOUT], s_sq[DOUT];

    const int tid = threadIdx.x;
    const int e0 = blockIdx.x * BM;

    for (int i = tid; i < BM; i += 256) {
        int e = min(e0 + i, E - 1);
        s_src[i] = esrc[e];
        s_dst[i] = edst[e];
    }
    if (tid < DOUT) { s_sum[tid] = 0.f; s_sq[tid] = 0.f; }
    __syncthreads();

    const int tx = tid & 15;         // output-column group (8 cols each)
    const int ty = tid >> 4;         // edge-row group (8 rows each)

    float acc[8][8];
    #pragma unroll
    for (int i = 0; i < 8; ++i)
        #pragma unroll
        for (int j = 0; j < 8; ++j) acc[i][j] = 0.f;

    // chunk loader: 16 K-values. The 64-element region boundaries (src|dst|nbr)
    // are multiples of BK, so each float4 stays inside one source tensor.
    auto load_chunk = [&](int kc, int buf) {
        #pragma unroll
        for (int it = 0; it < 2; ++it) {
            int v = tid + it * 256;          // 512 float4's cover 128x16
            int row = v >> 2, q = v & 3;
            int kg = kc * BK + q * 4;
            const float* p;
            if (kg < 64)       p = atom + (size_t)s_src[row] * D_ATOM + kg;
            else if (kg < 128) p = atom + (size_t)s_dst[row] * D_ATOM + (kg - 64);
            else               p = nbr + (size_t)min(e0 + row, E - 1) * D_ATOM + (kg - 128);
            float4 val = *(const float4*)p;
            *(float4*)&As[buf][row][q * 4] = val;
        }
        #pragma unroll
        for (int it = 0; it < 2; ++it) {
            int v = tid + it * 256;          // 512 float4's cover 16x128
            int kr = v >> 5, c = (v & 31) * 4;
            *(float4*)&Ws[buf][kr][c] =
                *(const float4*)(W + (size_t)(kc * BK + kr) * DOUT + c);
        }
    };

    load_chunk(0, 0);
    __syncthreads();

    const int nk = DIN / BK;  // 12
    #pragma unroll 1
    for (int kc = 0; kc < nk; ++kc) {
        int buf = kc & 1;
        if (kc + 1 < nk) load_chunk(kc + 1, buf ^ 1);
        #pragma unroll
        for (int k = 0; k < BK; ++k) {
            float a[8], w[8];
            #pragma unroll
            for (int i = 0; i < 8; ++i) a[i] = As[buf][ty * 8 + i][k];
            *(float4*)&w[0] = *(const float4*)&Ws[buf][k][tx * 8];
            *(float4*)&w[4] = *(const float4*)&Ws[buf][k][tx * 8 + 4];
            #pragma unroll
            for (int i = 0; i < 8; ++i)
                #pragma unroll
                for (int j = 0; j < 8; ++j)
                    acc[i][j] += a[i] * w[j];
        }
        __syncthreads();
    }

    // epilogue: bias, write z, accumulate per-column sum/sumsq
    float bb[8];
    #pragma unroll
    for (int j = 0; j < 8; ++j) bb[j] = __ldg(&bias[tx * 8 + j]);

    float csum[8], csq[8];
    #pragma unroll
    for (int j = 0; j < 8; ++j) { csum[j] = 0.f; csq[j] = 0.f; }

    #pragma unroll
    for (int i = 0; i < 8; ++i) {
        int e = e0 + ty * 8 + i;
        if (e < E) {
            #pragma unroll
            for (int j = 0; j < 8; ++j) {
                float v = acc[i][j] + bb[j];
                acc[i][j] = v;
                csum[j] += v;
                csq[j] += v * v;
            }
            float* zp = g_z + (size_t)e * DOUT + tx * 8;
            ((float4*)zp)[0] = make_float4(acc[i][0], acc[i][1], acc[i][2], acc[i][3]);
            ((float4*)zp)[1] = make_float4(acc[i][4], acc[i][5], acc[i][6], acc[i][7]);
        }
    }
    #pragma unroll
    for (int j = 0; j < 8; ++j) {
        atomicAdd(&s_sum[tx * 8 + j], csum[j]);
        atomicAdd(&s_sq[tx * 8 + j], csq[j]);
    }
    __syncthreads();
    if (tid < DOUT) {
        atomicAdd(&g_stats1[tid], s_sum[tid]);
        atomicAdd(&g_stats1[DOUT + tid], s_sq[tid]);
    }
}

// ---- 2: fold BN1 stats into affine scale/shift ----
__global__ void finalize1_kernel(const float* __restrict__ gamma,
                                 const float* __restrict__ beta, int E) {
    int j = threadIdx.x;   // 128
    float inv_e = 1.f / (float)E;
    float mean = g_stats1[j] * inv_e;
    float var = g_stats1[DOUT + j] * inv_e - mean * mean;
    float sc = rsqrtf(var + 1e-5f) * gamma[j];
    g_scale1[j] = sc;
    g_shift1[j] = beta[j] - mean * sc;
}

// ---- 3: normalize, gate (sigmoid*softplus), scatter-add ----
// one thread handles 4 columns of one edge (float4 reads of z)
__global__ void msg_kernel(const int* __restrict__ edst, int E) {
    long long idx = (long long)blockIdx.x * blockDim.x + threadIdx.x;
    long long tot = (long long)E * (D_ATOM / 4);
    if (idx >= tot) return;
    int e = (int)(idx >> 4);
    int j4 = (int)(idx & 15) * 4;
    const float* zp = g_z + (size_t)e * DOUT;
    float4 f = *(const float4*)(zp + j4);
    float4 c = *(const float4*)(zp + 64 + j4);
    float* up = g_upd + (size_t)__ldg(&edst[e]) * D_ATOM + j4;
    #pragma unroll
    for (int t = 0; t < 4; ++t) {
        float fv = (&f.x)[t] * __ldg(&g_scale1[j4 + t]) + __ldg(&g_shift1[j4 + t]);
        float cv = (&c.x)[t] * __ldg(&g_scale1[64 + j4 + t]) + __ldg(&g_shift1[64 + j4 + t]);
        float sig = 1.f / (1.f + expf(-fv));
        atomicAdd(up + t, sig * softplus_f(cv));
    }
}

// ---- 4: BN2 statistics over atoms ----
__global__ void bn2_stats_kernel(int N) {
    int j = threadIdx.x;  // 64
    float s = 0.f, q = 0.f;
    for (int a = blockIdx.x; a < N; a += gridDim.x) {
        float v = g_upd[(size_t)a * D_ATOM + j];
        s += v; q += v * v;
    }
    atomicAdd(&g_stats2[j], s);
    atomicAdd(&g_stats2[D_ATOM + j], q);
}

__global__ void finalize2_kernel(const float* __restrict__ gamma,
                                 const float* __restrict__ beta, int N) {
    int j = threadIdx.x;  // 64
    float inv_n = 1.f / (float)N;
    float mean = g_stats2[j] * inv_n;
    float var = g_stats2[D_ATOM + j] * inv_n - mean * mean;
    float sc = rsqrtf(var + 1e-5f) * gamma[j];
    g_scale2[j] = sc;
    g_shift2[j] = beta[j] - mean * sc;
}

// ---- 5: out = softplus(atom_in + BN2(update)) ----
__global__ void out_kernel(const float* __restrict__ atom, float* __restrict__ out, int N) {
    int idx = blockIdx.x * blockDim.x + threadIdx.x;
    if (idx >= N * D_ATOM) return;
    int j = idx & (D_ATOM - 1);
    float u = g_upd[idx] * g_scale2[j] + g_shift2[j];
    out[idx] = softplus_f(atom[idx] + u);
}

extern "C" void kernel_launch(void* const* d_in, const int* in_sizes, int n_in,
                              void* d_out, int out_size) {
    const float* atom = (const float*)d_in[0];
    const float* nbr  = (const float*)d_in[1];
    const int* esrc   = (const int*)d_in[2];
    const int* edst   = (const int*)d_in[3];
    const float* W    = (const float*)d_in[4];
    const float* b    = (const float*)d_in[5];
    const float* g1   = (const float*)d_in[6];
    const float* b1   = (const float*)d_in[7];
    const float* g2   = (const float*)d_in[8];
    const float* b2   = (const float*)d_in[9];
    float* out = (float*)d_out;

    int N = in_sizes[0] / D_ATOM;
    int E = in_sizes[2];

    init_kernel<<<(N * D_ATOM + 255) / 256, 256>>>(N * D_ATOM);
    gemm_kernel<<<(E + BM - 1) / BM, 256>>>(atom, nbr, esrc, edst, W, b, E);
    finalize1_kernel<<<1, DOUT>>>(g1, b1, E);
    long long msg_work = (long long)E * (D_ATOM / 4);
    msg_kernel<<<(unsigned)((msg_work + 255) / 256), 256>>>(edst, E);
    bn2_stats_kernel<<<256, D_ATOM>>>(N);
    finalize2_kernel<<<1, D_ATOM>>>(g2, b2, N);
    out_kernel<<<(N * D_ATOM + 255) / 256, 256>>>(atom, out, N);
}

// round 9
// speedup vs baseline: 2.3577x; 2.3577x over previous
#include <cuda_runtime.h>
#include <cuda_fp16.h>
#include <cuda_bf16.h>
#include <math.h>
#include <stdint.h>

#define D_ATOM 64
#define DOUT   128
#define MAX_E  1600000
#define MAX_N  50000

// ---- scratch (device globals: allocation-free contract) ----
__device__ __half g_zh[(size_t)MAX_E * DOUT];      // pre-BN GEMM output, fp16, 409MB
__device__ float  g_P[(size_t)MAX_N * 256];        // [P1 | P2] per atom, 51MB (L2-resident)
__device__ float  g_upd[(size_t)MAX_N * D_ATOM];   // scatter-add accumulator
__device__ float  g_stats1[2 * DOUT];
__device__ float  g_scale1[DOUT];
__device__ float  g_shift1[DOUT];
__device__ float  g_stats2[2 * D_ATOM];
__device__ float  g_scale2[D_ATOM];
__device__ float  g_shift2[D_ATOM];
// W3^T (n-major [128][64] bf16, SW128-swizzled smem images), hi/lo split
__device__ __align__(16) unsigned char g_W3h[16384];
__device__ __align__(16) unsigned char g_W3l[16384];

#define SWZ(o) ((o) ^ (((o) >> 3) & 0x70))

__device__ __forceinline__ uint32_t smem_u32(const void* p) {
    uint32_t a;
    asm("{ .reg .u64 t; cvta.to.shared.u64 t, %1; cvt.u32.u64 %0, t; }"
        : "=r"(a) : "l"(p));
    return a;
}

// m16n8k16 bf16 MMA, fp32 accum (sm_80+ PTX, compiles for plain compute_103)
__device__ __forceinline__ void mma_bf16(float* c, const uint32_t* a,
                                         uint32_t b0, uint32_t b1) {
    asm volatile(
        "mma.sync.aligned.m16n8k16.row.col.f32.bf16.bf16.f32 "
        "{%0,%1,%2,%3}, {%4,%5,%6,%7}, {%8,%9}, {%0,%1,%2,%3};"
        : "+f"(c[0]), "+f"(c[1]), "+f"(c[2]), "+f"(c[3])
        : "r"(a[0]), "r"(a[1]), "r"(a[2]), "r"(a[3]), "r"(b0), "r"(b1));
}
__device__ __forceinline__ void ldm4(uint32_t* r, uint32_t addr) {
    asm volatile("ldmatrix.sync.aligned.m8n8.x4.shared.b16 {%0,%1,%2,%3}, [%4];"
                 : "=r"(r[0]), "=r"(r[1]), "=r"(r[2]), "=r"(r[3]) : "r"(addr));
}

__device__ __forceinline__ float softplus_fast(float x) {
    return fmaxf(x, 0.f) + __logf(1.f + __expf(-fabsf(x)));
}
__device__ __forceinline__ void split_bf16(float v, unsigned short& h, unsigned short& l) {
    __nv_bfloat16 hb = __float2bfloat16(v);
    h = __bfloat16_as_ushort(hb);
    l = __bfloat16_as_ushort(__float2bfloat16(v - __bfloat162float(hb)));
}

// ---- W prep: W3^T hi/lo swizzled smem images ----
__global__ void wprep_kernel(const float* __restrict__ W) {
    int idx = blockIdx.x * blockDim.x + threadIdx.x;
    if (idx >= 128 * 64) return;
    int n = idx >> 6, k = idx & 63;
    float v = W[(size_t)(128 + k) * 128 + n];
    unsigned short h, l;
    split_bf16(v, h, l);
    uint32_t off = SWZ((uint32_t)(n * 128 + k * 2));
    *(unsigned short*)(g_W3h + off) = h;
    *(unsigned short*)(g_W3l + off) = l;
}

// ---- 0: zero accumulators ----
__global__ void init_kernel(int n_upd) {
    int i = blockIdx.x * blockDim.x + threadIdx.x;
    if (i < n_upd) g_upd[i] = 0.f;
    if (i < 2 * DOUT) g_stats1[i] = 0.f;
    if (i < 2 * D_ATOM) g_stats2[i] = 0.f;
}

// ---- 1: P = atom @ [W1|W2]  ([N,64]@[64,256], SIMT fp32, exact) ----
// grid (ceil(N/128), 2): y selects W1 (rows 0..63) or W2 (rows 64..127)
#define PG_SMEM (128 * 68 * 4 + 64 * 136 * 4)
__global__ __launch_bounds__(256, 2)
void pgemm_kernel(const float* __restrict__ atom, const float* __restrict__ W, int N) {
    extern __shared__ __align__(16) unsigned char smem_raw[];
    float* As = (float*)smem_raw;                 // [128][68]
    float* Ws = (float*)(smem_raw + 128 * 68 * 4); // [64][136]
    const int tid = threadIdx.x;
    const int a0 = blockIdx.x * 128;
    const int half = blockIdx.y;

    #pragma unroll
    for (int it = 0; it < 8; ++it) {             // A tile 128x64
        int v = tid + it * 256;
        int row = v >> 4, q = v & 15;
        float4 x = *(const float4*)(atom + (size_t)min(a0 + row, N - 1) * 64 + q * 4);
        *(float4*)&As[row * 68 + q * 4] = x;
    }
    #pragma unroll
    for (int it = 0; it < 8; ++it) {             // W tile 64x128
        int v = tid + it * 256;
        int k = v >> 5, q = v & 31;
        *(float4*)&Ws[k * 136 + q * 4] =
            *(const float4*)(W + (size_t)(half * 64 + k) * 128 + q * 4);
    }
    __syncthreads();

    const int tx = tid & 15, ty = tid >> 4;
    float acc[8][8];
    #pragma unroll
    for (int i = 0; i < 8; ++i)
        #pragma unroll
        for (int j = 0; j < 8; ++j) acc[i][j] = 0.f;

    #pragma unroll 4
    for (int k = 0; k < 64; ++k) {
        float a[8], w[8];
        #pragma unroll
        for (int i = 0; i < 8; ++i) a[i] = As[(ty * 8 + i) * 68 + k];
        *(float4*)&w[0] = *(const float4*)&Ws[k * 136 + tx * 8];
        *(float4*)&w[4] = *(const float4*)&Ws[k * 136 + tx * 8 + 4];
        #pragma unroll
        for (int i = 0; i < 8; ++i)
            #pragma unroll
            for (int j = 0; j < 8; ++j) acc[i][j] += a[i] * w[j];
    }
    #pragma unroll
    for (int i = 0; i < 8; ++i) {
        int a = a0 + ty * 8 + i;
        if (a < N) {
            float* dst = g_P + (size_t)a * 256 + half * 128 + tx * 8;
            ((float4*)dst)[0] = make_float4(acc[i][0], acc[i][1], acc[i][2], acc[i][3]);
            ((float4*)dst)[1] = make_float4(acc[i][4], acc[i][5], acc[i][6], acc[i][7]);
    }
    }
}

// ---- 2: edge GEMM: z = nbr@W3 + P1[src] + P2[dst] + b, fp16 z, BN1 stats ----
// CTA: 128 edges x 128 cols, K=64. 8 warps in 2(m) x 4(n); warp tile 64x32.
// smem: A_hi@0 A_lo@16K B_hi@32K B_lo@48K src@65536 dst@66048 bias@66560 red@67072
#define EG_SMEM 68096
__global__ __launch_bounds__(256, 2)
void egemm_kernel(const float* __restrict__ nbr, const int* __restrict__ esrc,
                  const int* __restrict__ edst, const float* __restrict__ bias, int E)
{
    extern __shared__ __align__(16) unsigned char smem_raw[];
    const uint32_t sb = smem_u32(smem_raw);
    int*   s_src  = (int*)(smem_raw + 65536);
    int*   s_dst  = (int*)(smem_raw + 66048);
    float* s_bias = (float*)(smem_raw + 66560);
    float* s_red  = (float*)(smem_raw + 67072);  // [256]: sum | sumsq

    const int tid = threadIdx.x, lane = tid & 31, wid = tid >> 5;
    const int warp_m = wid & 1, warp_n = wid >> 1;
    const int e0 = blockIdx.x * 128;

    if (tid < 128) {
        int e = min(e0 + tid, E - 1);
        s_src[tid] = esrc[e]; s_dst[tid] = edst[e]; s_bias[tid] = bias[tid];
    }
    s_red[tid] = 0.f;

    // B images (L2-hot, pre-swizzled)
    #pragma unroll
    for (int it = 0; it < 4; ++it) {
        int i = tid + it * 256;
        ((uint4*)(smem_raw + 32768))[i] = ((const uint4*)g_W3h)[i];
        ((uint4*)(smem_raw + 49152))[i] = ((const uint4*)g_W3l)[i];
    }
    // A: nbr rows (sequential, coalesced) -> hi/lo bf16, SW128 swizzle
    #pragma unroll
    for (int it = 0; it < 4; ++it) {
        int u = tid + it * 256;              // 1024 units of 8 cols
        int row = u >> 3, g = u & 7;
        const float* p = nbr + (size_t)min(e0 + row, E - 1) * 64 + g * 8;
        float4 x0 = __ldg((const float4*)p);
        float4 x1 = __ldg((const float4*)p + 1);
        float v[8] = {x0.x, x0.y, x0.z, x0.w, x1.x, x1.y, x1.z, x1.w};
        uint32_t hp[4], lp[4];
        #pragma unroll
        for (int q = 0; q < 4; ++q) {
            unsigned short h0, l0, h1, l1;
            split_bf16(v[2 * q], h0, l0);
            split_bf16(v[2 * q + 1], h1, l1);
            hp[q] = (uint32_t)h0 | ((uint32_t)h1 << 16);
            lp[q] = (uint32_t)l0 | ((uint32_t)l1 << 16);
        }
        uint32_t off = SWZ((uint32_t)(row * 128 + g * 16));
        *(uint4*)(smem_raw + off)         = make_uint4(hp[0], hp[1], hp[2], hp[3]);
        *(uint4*)(smem_raw + 16384 + off) = make_uint4(lp[0], lp[1], lp[2], lp[3]);
    }
    __syncthreads();

    float c[4][4][4];
    #pragma unroll
    for (int mf = 0; mf < 4; ++mf)
        #pragma unroll
        for (int nf = 0; nf < 4; ++nf)
            #pragma unroll
            for (int t = 0; t < 4; ++t) c[mf][nf][t] = 0.f;

    // ldmatrix per-lane addressing components
    const int a_row = (lane & 15);             // + (lane>=16 -> +16B col)
    const int a_cb  = (lane & 16);
    const int b_row = ((lane & 16) >> 1) + (lane & 7);
    const int b_cb  = ((lane & 8) << 1);

    #pragma unroll
    for (int ks = 0; ks < 4; ++ks) {           // K = 4 x 16
        uint32_t ah[4][4], al[4][4];
        #pragma unroll
        for (int mf = 0; mf < 4; ++mf) {
            int row = warp_m * 64 + mf * 16 + a_row;
            uint32_t off = SWZ((uint32_t)(row * 128 + ks * 32 + a_cb));
            ldm4(ah[mf], sb + off);
            ldm4(al[mf], sb + 16384 + off);
        }
        uint32_t bh[2][4], bl[2][4];
        #pragma unroll
        for (int nb = 0; nb < 2; ++nb) {
            int row = warp_n * 32 + nb * 16 + b_row;
            uint32_t off = SWZ((uint32_t)(row * 128 + ks * 32 + b_cb));
            ldm4(bh[nb], sb + 32768 + off);
            ldm4(bl[nb], sb + 49152 + off);
        }
        #pragma unroll
        for (int mf = 0; mf < 4; ++mf)
            #pragma unroll
            for (int nf = 0; nf < 4; ++nf) {
                int nb = nf >> 1, s = (nf & 1) << 1;
                mma_bf16(c[mf][nf], ah[mf], bh[nb][s], bh[nb][s + 1]);  // hi*hi
                mma_bf16(c[mf][nf], ah[mf], bl[nb][s], bl[nb][s + 1]);  // hi*lo
                mma_bf16(c[mf][nf], al[mf], bh[nb][s], bh[nb][s + 1]);  // lo*hi
            }
    }

    // epilogue: + P1[src] + P2[dst] + bias, fp16 z, BN1 stats
    float se[4], so[4], qe[4], qo[4];
    #pragma unroll
    for (int nf = 0; nf < 4; ++nf) { se[nf] = so[nf] = qe[nf] = qo[nf] = 0.f; }

    #pragma unroll
    for (int mf = 0; mf < 4; ++mf) {
        int lr0 = warp_m * 64 + mf * 16 + (lane >> 2);
        int lr1 = lr0 + 8;
        bool v0 = (e0 + lr0) < E, v1 = (e0 + lr1) < E;
        const float* P1a = g_P + (size_t)s_src[lr0] * 256;
        const float* P2a = g_P + (size_t)s_dst[lr0] * 256 + 128;
        const float* P1b = g_P + (size_t)s_src[lr1] * 256;
        const float* P2b = g_P + (size_t)s_dst[lr1] * 256 + 128;
        __half* z0 = g_zh + (size_t)(e0 + lr0) * 128;
        __half* z1 = g_zh + (size_t)(e0 + lr1) * 128;
        #pragma unroll
        for (int nf = 0; nf < 4; ++nf) {
            int cc = warp_n * 32 + nf * 8 + (lane & 3) * 2;
            float b0 = s_bias[cc], b1 = s_bias[cc + 1];
            float2 pa1 = __ldg((const float2*)(P1a + cc));
            float2 pa2 = __ldg((const float2*)(P2a + cc));
            float z00 = c[mf][nf][0] + pa1.x + pa2.x + b0;
            float z01 = c[mf][nf][1] + pa1.y + pa2.y + b1;
            float2 pb1 = __ldg((const float2*)(P1b + cc));
            float2 pb2 = __ldg((const float2*)(P2b + cc));
            float z10 = c[mf][nf][2] + pb1.x + pb2.x + b0;
            float z11 = c[mf][nf][3] + pb1.y + pb2.y + b1;
            if (v0) *(__half2*)(z0 + cc) = __floats2half2_rn(z00, z01);
            if (v1) *(__half2*)(z1 + cc) = __floats2half2_rn(z10, z11);
            float m00 = v0 ? z00 : 0.f, m01 = v0 ? z01 : 0.f;
            float m10 = v1 ? z10 : 0.f, m11 = v1 ? z11 : 0.f;
            se[nf] += m00 + m10;
            so[nf] += m01 + m11;
            qe[nf] += m00 * m00 + m10 * m10;
            qo[nf] += m01 * m01 + m11 * m11;
        }
    }
    // reduce across the 8 lanes sharing each column (lane>>2 varies)
    #pragma unroll
    for (int nf = 0; nf < 4; ++nf) {
        #pragma unroll
        for (int o = 4; o < 32; o <<= 1) {
            se[nf] += __shfl_xor_sync(0xFFFFFFFFu, se[nf], o);
            so[nf] += __shfl_xor_sync(0xFFFFFFFFu, so[nf], o);
            qe[nf] += __shfl_xor_sync(0xFFFFFFFFu, qe[nf], o);
            qo[nf] += __shfl_xor_sync(0xFFFFFFFFu, qo[nf], o);
        }
        if (lane < 4) {
            int cc = warp_n * 32 + nf * 8 + lane * 2;
            atomicAdd(&s_red[cc], se[nf]);
            atomicAdd(&s_red[cc + 1], so[nf]);
            atomicAdd(&s_red[128 + cc], qe[nf]);
            atomicAdd(&s_red[128 + cc + 1], qo[nf]);
        }
    }
    __syncthreads();
    atomicAdd(&g_stats1[tid], s_red[tid]);
}

// ---- 3: fold BN1 stats ----
__global__ void finalize1_kernel(const float* __restrict__ gamma,
                                 const float* __restrict__ beta, int E) {
    int j = threadIdx.x;
    float inv_e = 1.f / (float)E;
    float mean = g_stats1[j] * inv_e;
    float var = g_stats1[DOUT + j] * inv_e - mean * mean;
    float sc = rsqrtf(var + 1e-5f) * gamma[j];
    g_scale1[j] = sc;
    g_shift1[j] = beta[j] - mean * sc;
}

// ---- 4: normalize, gate, scatter-add (8 cols/thread, fp16 z) ----
__global__ void msg_kernel(const int* __restrict__ edst, int E) {
    long long idx = (long long)blockIdx.x * blockDim.x + threadIdx.x;
    if (idx >= (long long)E * 8) return;
    int e = (int)(idx >> 3);
    int j8 = (int)(idx & 7) * 8;
    const __half* zp = g_zh + (size_t)e * 128;
    uint4 fr = *(const uint4*)(zp + j8);
    uint4 cr = *(const uint4*)(zp + 64 + j8);
    const __half2* fh = (const __half2*)&fr;
    const __half2* ch = (const __half2*)&cr;
    float fv[8], cv[8];
    #pragma unroll
    for (int q = 0; q < 4; ++q) {
        float2 t = __half22float2(fh[q]); fv[2 * q] = t.x; fv[2 * q + 1] = t.y;
        float2 u = __half22float2(ch[q]); cv[2 * q] = u.x; cv[2 * q + 1] = u.y;
    }
    float* up = g_upd + (size_t)__ldg(&edst[e]) * D_ATOM + j8;
    #pragma unroll
    for (int t = 0; t < 8; ++t) {
        float a = fv[t] * __ldg(&g_scale1[j8 + t]) + __ldg(&g_shift1[j8 + t]);
        float b = cv[t] * __ldg(&g_scale1[64 + j8 + t]) + __ldg(&g_shift1[64 + j8 + t]);
        float sig = __fdividef(1.f, 1.f + __expf(-a));
        atomicAdd(up + t, sig * softplus_fast(b));
    }
}

// ---- 5: BN2 stats ----
__global__ void bn2_stats_kernel(int N) {
    int j = threadIdx.x & 63;
    int rl = blockIdx.x * (blockDim.x >> 6) + (threadIdx.x >> 6);
    int stride = gridDim.x * (blockDim.x >> 6);
    float s = 0.f, q = 0.f;
    for (int a = rl; a < N; a += stride) {
        float v = g_upd[(size_t)a * D_ATOM + j];
        s += v; q += v * v;
    }
    atomicAdd(&g_stats2[j], s);
    atomicAdd(&g_stats2[D_ATOM + j], q);
}

__global__ void finalize2_kernel(const float* __restrict__ gamma,
                                 const float* __restrict__ beta, int N) {
    int j = threadIdx.x;
    float inv_n = 1.f / (float)N;
    float mean = g_stats2[j] * inv_n;
    float var = g_stats2[D_ATOM + j] * inv_n - mean * mean;
    float sc = rsqrtf(var + 1e-5f) * gamma[j];
    g_scale2[j] = sc;
    g_shift2[j] = beta[j] - mean * sc;
}

// ---- 6: out = softplus(atom_in + BN2(update)) ----
__global__ void out_kernel(const float* __restrict__ atom, float* __restrict__ out, int N) {
    int idx = blockIdx.x * blockDim.x + threadIdx.x;
    if (idx >= N * D_ATOM) return;
    int j = idx & (D_ATOM - 1);
    float u = g_upd[idx] * g_scale2[j] + g_shift2[j];
    float x = atom[idx] + u;
    out[idx] = fmaxf(x, 0.f) + log1pf(expf(-fabsf(x)));
}

extern "C" void kernel_launch(void* const* d_in, const int* in_sizes, int n_in,
                              void* d_out, int out_size) {
    const float* atom = (const float*)d_in[0];
    const float* nbr  = (const float*)d_in[1];
    const int* esrc   = (const int*)d_in[2];
    const int* edst   = (const int*)d_in[3];
    const float* W    = (const float*)d_in[4];
    const float* b    = (const float*)d_in[5];
    const float* g1   = (const float*)d_in[6];
    const float* b1   = (const float*)d_in[7];
    const float* g2   = (const float*)d_in[8];
    const float* b2   = (const float*)d_in[9];
    float* out = (float*)d_out;

    int N = in_sizes[0] / D_ATOM;
    int E = in_sizes[2];

    cudaFuncSetAttribute(pgemm_kernel, cudaFuncAttributeMaxDynamicSharedMemorySize, PG_SMEM);
    cudaFuncSetAttribute(egemm_kernel, cudaFuncAttributeMaxDynamicSharedMemorySize, EG_SMEM);

    wprep_kernel<<<(128 * 64 + 255) / 256, 256>>>(W);
    init_kernel<<<(N * D_ATOM + 255) / 256, 256>>>(N * D_ATOM);
    dim3 pg((N + 127) / 128, 2);
    pgemm_kernel<<<pg, 256, PG_SMEM>>>(atom, W, N);
    egemm_kernel<<<(E + 127) / 128, 256, EG_SMEM>>>(nbr, esrc, edst, b, E);
    finalize1_kernel<<<1, DOUT>>>(g1, b1, E);
    long long msg_work = (long long)E * 8;
    msg_kernel<<<(unsigned)((msg_work + 255) / 256), 256>>>(edst, E);
    bn2_stats_kernel<<<256, 256>>>(N);
    finalize2_kernel<<<1, D_ATOM>>>(g2, b2, N);
    out_kernel<<<(N * D_ATOM + 255) / 256, 256>>>(atom, out, N);
}

// round 11
// speedup vs baseline: 2.5620x; 1.0866x over previous
#include <cuda_runtime.h>
#include <cuda_fp16.h>
#include <math.h>
#include <stdint.h>

#define D_ATOM 64
#define DOUT   128
#define MAX_E  1600000
#define MAX_N  50000

// ---- scratch (device globals: allocation-free contract) ----
__device__ __half g_zh[(size_t)MAX_E * DOUT];      // pre-BN GEMM output, fp16, 409MB
__device__ __half g_P[(size_t)MAX_N * 256];        // [P1 | P2] per atom, fp16, 25.6MB
__device__ float  g_upd[(size_t)MAX_N * D_ATOM];   // scatter-add accumulator
__device__ float  g_stats1[2 * DOUT];
__device__ float  g_scale1[DOUT];
__device__ float  g_shift1[DOUT];
__device__ float  g_stats2[2 * D_ATOM];
__device__ float  g_scale2[D_ATOM];
__device__ float  g_shift2[D_ATOM];
// W3^T (n-major [128][64] f16, SW128-swizzled smem image)
__device__ __align__(16) unsigned char g_W3[16384];

#define SWZ(o) ((o) ^ (((o) >> 3) & 0x70))

__device__ __forceinline__ uint32_t smem_u32(const void* p) {
    uint32_t a;
    asm("{ .reg .u64 t; cvta.to.shared.u64 t, %1; cvt.u32.u64 %0, t; }"
        : "=r"(a) : "l"(p));
    return a;
}

// m16n8k16 fp16 MMA, fp32 accum
__device__ __forceinline__ void mma_f16(float* c, const uint32_t* a,
                                        uint32_t b0, uint32_t b1) {
    asm volatile(
        "mma.sync.aligned.m16n8k16.row.col.f32.f16.f16.f32 "
        "{%0,%1,%2,%3}, {%4,%5,%6,%7}, {%8,%9}, {%0,%1,%2,%3};"
        : "+f"(c[0]), "+f"(c[1]), "+f"(c[2]), "+f"(c[3])
        : "r"(a[0]), "r"(a[1]), "r"(a[2]), "r"(a[3]), "r"(b0), "r"(b1));
}
__device__ __forceinline__ void ldm4(uint32_t* r, uint32_t addr) {
    asm volatile("ldmatrix.sync.aligned.m8n8.x4.shared.b16 {%0,%1,%2,%3}, [%4];"
                 : "=r"(r[0]), "=r"(r[1]), "=r"(r[2]), "=r"(r[3]) : "r"(addr));
}

__device__ __forceinline__ float softplus_fast(float x) {
    return fmaxf(x, 0.f) + __logf(1.f + __expf(-fabsf(x)));
}

// ---- W prep: W3^T f16 swizzled smem image ----
__global__ void wprep_kernel(const float* __restrict__ W) {
    int idx = blockIdx.x * blockDim.x + threadIdx.x;
    if (idx >= 128 * 64) return;
    int n = idx >> 6, k = idx & 63;
    float v = W[(size_t)(128 + k) * 128 + n];
    uint32_t off = SWZ((uint32_t)(n * 128 + k * 2));
    *(unsigned short*)(g_W3 + off) = __half_as_ushort(__float2half_rn(v));
}

// ---- 0: zero accumulators ----
__global__ void init_kernel(int n_upd) {
    int i = blockIdx.x * blockDim.x + threadIdx.x;
    if (i < n_upd) g_upd[i] = 0.f;
    if (i < 2 * DOUT) g_stats1[i] = 0.f;
    if (i < 2 * D_ATOM) g_stats2[i] = 0.f;
}

// ---- 1: P = atom @ [W1|W2]  ([N,64]@[64,256], SIMT fp32), store fp16 ----
#define PG_SMEM (128 * 68 * 4 + 64 * 136 * 4)
__global__ __launch_bounds__(256, 2)
void pgemm_kernel(const float* __restrict__ atom, const float* __restrict__ W, int N) {
    extern __shared__ __align__(16) unsigned char smem_raw[];
    float* As = (float*)smem_raw;                  // [128][68]
    float* Ws = (float*)(smem_raw + 128 * 68 * 4); // [64][136]
    const int tid = threadIdx.x;
    const int a0 = blockIdx.x * 128;
    const int hsel = blockIdx.y;

    #pragma unroll
    for (int it = 0; it < 8; ++it) {
        int v = tid + it * 256;
        int row = v >> 4, q = v & 15;
        float4 x = *(const float4*)(atom + (size_t)min(a0 + row, N - 1) * 64 + q * 4);
        *(float4*)&As[row * 68 + q * 4] = x;
    }
    #pragma unroll
    for (int it = 0; it < 8; ++it) {
        int v = tid + it * 256;
        int k = v >> 5, q = v & 31;
        *(float4*)&Ws[k * 136 + q * 4] =
            *(const float4*)(W + (size_t)(hsel * 64 + k) * 128 + q * 4);
    }
    __syncthreads();

    const int tx = tid & 15, ty = tid >> 4;
    float acc[8][8];
    #pragma unroll
    for (int i = 0; i < 8; ++i)
        #pragma unroll
        for (int j = 0; j < 8; ++j) acc[i][j] = 0.f;

    #pragma unroll 4
    for (int k = 0; k < 64; ++k) {
        float a[8], w[8];
        #pragma unroll
        for (int i = 0; i < 8; ++i) a[i] = As[(ty * 8 + i) * 68 + k];
        *(float4*)&w[0] = *(const float4*)&Ws[k * 136 + tx * 8];
        *(float4*)&w[4] = *(const float4*)&Ws[k * 136 + tx * 8 + 4];
        #pragma unroll
        for (int i = 0; i < 8; ++i)
            #pragma unroll
            for (int j = 0; j < 8; ++j) acc[i][j] += a[i] * w[j];
    }
    #pragma unroll
    for (int i = 0; i < 8; ++i) {
        int a = a0 + ty * 8 + i;
        if (a < N) {
            __half2 h[4];
            #pragma unroll
            for (int q = 0; q < 4; ++q)
                h[q] = __floats2half2_rn(acc[i][2 * q], acc[i][2 * q + 1]);
            *(uint4*)(g_P + (size_t)a * 256 + hsel * 128 + tx * 8) = *(uint4*)h;
        }
    }
}

// ---- 2: edge GEMM: z = nbr@W3 + P1[src] + P2[dst] + b (fp16 MMA), BN1 stats ----
// smem: A img @0 (16K), B img @16384 (16K); P stage @0 (2*128*136 halves = 68K,
// overlaps images after mainloop); tail @69632: src,dst,bias,red
#define EG_PSTR   17408   // halves per P table (128*136)
#define EG_TAIL   69632
#define EG_SMEM   (EG_TAIL + 2560)
__global__ __launch_bounds__(256, 2)
void egemm_kernel(const float* __restrict__ nbr, const int* __restrict__ esrc,
                  const int* __restrict__ edst, const float* __restrict__ bias, int E)
{
    extern __shared__ __align__(16) unsigned char smem_raw[];
    const uint32_t sb = smem_u32(smem_raw);
    int*   s_src  = (int*)(smem_raw + EG_TAIL);
    int*   s_dst  = (int*)(smem_raw + EG_TAIL + 512);
    float* s_bias = (float*)(smem_raw + EG_TAIL + 1024);
    float* s_red  = (float*)(smem_raw + EG_TAIL + 1536);  // [256]: sum | sumsq
    __half* sP    = (__half*)smem_raw;                     // P stage (post-mainloop)

    const int tid = threadIdx.x, lane = tid & 31, wid = tid >> 5;
    const int warp_m = wid & 1, warp_n = wid >> 1;
    const int e0 = blockIdx.x * 128;

    if (tid < 128) {
        int e = min(e0 + tid, E - 1);
        s_src[tid] = esrc[e]; s_dst[tid] = edst[e]; s_bias[tid] = bias[tid];
    }
    s_red[tid] = 0.f;

    // B image (L2-hot, pre-swizzled f16): 16KB
    #pragma unroll
    for (int it = 0; it < 4; ++it) {
        int i = tid + it * 256;
        ((uint4*)(smem_raw + 16384))[i] = ((const uint4*)g_W3)[i];
    }
    // A: nbr rows -> f16, SW128 swizzle (128 rows x 64 cols x 2B)
    #pragma unroll
    for (int it = 0; it < 4; ++it) {
        int u = tid + it * 256;              // 1024 units of 8 cols
        int row = u >> 3, g = u & 7;
        const float* p = nbr + (size_t)min(e0 + row, E - 1) * 64 + g * 8;
        float4 x0 = __ldg((const float4*)p);
        float4 x1 = __ldg((const float4*)p + 1);
        __half2 h[4];
        h[0] = __floats2half2_rn(x0.x, x0.y);
        h[1] = __floats2half2_rn(x0.z, x0.w);
        h[2] = __floats2half2_rn(x1.x, x1.y);
        h[3] = __floats2half2_rn(x1.z, x1.w);
        uint32_t off = SWZ((uint32_t)(row * 128 + g * 16));
        *(uint4*)(smem_raw + off) = *(uint4*)h;
    }
    __syncthreads();

    float c[4][4][4];
    #pragma unroll
    for (int mf = 0; mf < 4; ++mf)
        #pragma unroll
        for (int nf = 0; nf < 4; ++nf)
            #pragma unroll
            for (int t = 0; t < 4; ++t) c[mf][nf][t] = 0.f;

    const int a_row = (lane & 15);
    const int a_cb  = (lane & 16);
    const int b_row = ((lane & 16) >> 1) + (lane & 7);
    const int b_cb  = ((lane & 8) << 1);

    #pragma unroll
    for (int ks = 0; ks < 4; ++ks) {           // K = 4 x 16
        uint32_t ah[4][4];
        #pragma unroll
        for (int mf = 0; mf < 4; ++mf) {
            int row = warp_m * 64 + mf * 16 + a_row;
            ldm4(ah[mf], sb + SWZ((uint32_t)(row * 128 + ks * 32 + a_cb)));
        }
        uint32_t bh[2][4];
        #pragma unroll
        for (int nb = 0; nb < 2; ++nb) {
            int row = warp_n * 32 + nb * 16 + b_row;
            ldm4(bh[nb], sb + 16384 + SWZ((uint32_t)(row * 128 + ks * 32 + b_cb)));
        }
        #pragma unroll
        for (int mf = 0; mf < 4; ++mf)
            #pragma unroll
            for (int nf = 0; nf < 4; ++nf) {
                int nb = nf >> 1, s = (nf & 1) << 1;
                mma_f16(c[mf][nf], ah[mf], bh[nb][s], bh[nb][s + 1]);
            }
    }
    __syncthreads();   // mainloop frags consumed; images can be overwritten

    // Stage P1|P2 tiles into smem, coalesced 16B loads (fp16, pad 136 halves)
    #pragma unroll
    for (int it = 0; it < 16; ++it) {
        int u = tid + it * 256;               // 4096 uint4 total
        int table = u >> 11, row = (u >> 4) & 127, q = u & 15;
        int aidx = table == 0 ? s_src[row] : s_dst[row];
        uint4 v = __ldg((const uint4*)(g_P + (size_t)aidx * 256 + table * 128 + q * 8));
        *(uint4*)(sP + table * EG_PSTR + row * 136 + q * 8) = v;
    }
    __syncthreads();

    // epilogue: + P1 + P2 + bias, fp16 z, BN1 stats
    float se[4], so[4], qe[4], qo[4];
    #pragma unroll
    for (int nf = 0; nf < 4; ++nf) { se[nf] = so[nf] = qe[nf] = qo[nf] = 0.f; }

    #pragma unroll
    for (int mf = 0; mf < 4; ++mf) {
        int lr0 = warp_m * 64 + mf * 16 + (lane >> 2);
        int lr1 = lr0 + 8;
        bool v0 = (e0 + lr0) < E, v1 = (e0 + lr1) < E;
        __half* z0 = g_zh + (size_t)(e0 + lr0) * 128;
        __half* z1 = g_zh + (size_t)(e0 + lr1) * 128;
        #pragma unroll
        for (int nf = 0; nf < 4; ++nf) {
            int cc = warp_n * 32 + nf * 8 + (lane & 3) * 2;
            float b0 = s_bias[cc], b1 = s_bias[cc + 1];
            float2 pa1 = __half22float2(*(__half2*)(sP + lr0 * 136 + cc));
            float2 pa2 = __half22float2(*(__half2*)(sP + EG_PSTR + lr0 * 136 + cc));
            float2 pb1 = __half22float2(*(__half2*)(sP + lr1 * 136 + cc));
            float2 pb2 = __half22float2(*(__half2*)(sP + EG_PSTR + lr1 * 136 + cc));
            float z00 = c[mf][nf][0] + pa1.x + pa2.x + b0;
            float z01 = c[mf][nf][1] + pa1.y + pa2.y + b1;
            float z10 = c[mf][nf][2] + pb1.x + pb2.x + b0;
            float z11 = c[mf][nf][3] + pb1.y + pb2.y + b1;
            if (v0) *(__half2*)(z0 + cc) = __floats2half2_rn(z00, z01);
            if (v1) *(__half2*)(z1 + cc) = __floats2half2_rn(z10, z11);
            float m00 = v0 ? z00 : 0.f, m01 = v0 ? z01 : 0.f;
            float m10 = v1 ? z10 : 0.f, m11 = v1 ? z11 : 0.f;
            se[nf] += m00 + m10;
            so[nf] += m01 + m11;
            qe[nf] += m00 * m00 + m10 * m10;
            qo[nf] += m01 * m01 + m11 * m11;
        }
    }
    #pragma unroll
    for (int nf = 0; nf < 4; ++nf) {
        #pragma unroll
        for (int o = 4; o < 32; o <<= 1) {
            se[nf] += __shfl_xor_sync(0xFFFFFFFFu, se[nf], o);
            so[nf] += __shfl_xor_sync(0xFFFFFFFFu, so[nf], o);
            qe[nf] += __shfl_xor_sync(0xFFFFFFFFu, qe[nf], o);
            qo[nf] += __shfl_xor_sync(0xFFFFFFFFu, qo[nf], o);
        }
        if (lane < 4) {
            int cc = warp_n * 32 + nf * 8 + lane * 2;
            atomicAdd(&s_red[cc], se[nf]);
            atomicAdd(&s_red[cc + 1], so[nf]);
            atomicAdd(&s_red[128 + cc], qe[nf]);
            atomicAdd(&s_red[128 + cc + 1], qo[nf]);
        }
    }
    __syncthreads();
    atomicAdd(&g_stats1[tid], s_red[tid]);
}

// ---- 3: fold BN1 stats ----
__global__ void finalize1_kernel(const float* __restrict__ gamma,
                                 const float* __restrict__ beta, int E) {
    int j = threadIdx.x;
    float inv_e = 1.f / (float)E;
    float mean = g_stats1[j] * inv_e;
    float var = g_stats1[DOUT + j] * inv_e - mean * mean;
    float sc = rsqrtf(var + 1e-5f) * gamma[j];
    g_scale1[j] = sc;
    g_shift1[j] = beta[j] - mean * sc;
}

// ---- 4: normalize, gate, scatter-add (8 cols/thread, fp16 z) ----
__global__ void msg_kernel(const int* __restrict__ edst, int E) {
    long long idx = (long long)blockIdx.x * blockDim.x + threadIdx.x;
    if (idx >= (long long)E * 8) return;
    int e = (int)(idx >> 3);
    int j8 = (int)(idx & 7) * 8;
    const __half* zp = g_zh + (size_t)e * 128;
    uint4 fr = *(const uint4*)(zp + j8);
    uint4 cr = *(const uint4*)(zp + 64 + j8);
    const __half2* fh = (const __half2*)&fr;
    const __half2* ch = (const __half2*)&cr;
    float fv[8], cv[8];
    #pragma unroll
    for (int q = 0; q < 4; ++q) {
        float2 t = __half22float2(fh[q]); fv[2 * q] = t.x; fv[2 * q + 1] = t.y;
        float2 u = __half22float2(ch[q]); cv[2 * q] = u.x; cv[2 * q + 1] = u.y;
    }
    float* up = g_upd + (size_t)__ldg(&edst[e]) * D_ATOM + j8;
    #pragma unroll
    for (int t = 0; t < 8; ++t) {
        float a = fv[t] * __ldg(&g_scale1[j8 + t]) + __ldg(&g_shift1[j8 + t]);
        float b = cv[t] * __ldg(&g_scale1[64 + j8 + t]) + __ldg(&g_shift1[64 + j8 + t]);
        float sig = __fdividef(1.f, 1.f + __expf(-a));
        atomicAdd(up + t, sig * softplus_fast(b));
    }
}

// ---- 5: BN2 stats ----
__global__ void bn2_stats_kernel(int N) {
    int j = threadIdx.x & 63;
    int rl = blockIdx.x * (blockDim.x >> 6) + (threadIdx.x >> 6);
    int stride = gridDim.x * (blockDim.x >> 6);
    float s = 0.f, q = 0.f;
    for (int a = rl; a < N; a += stride) {
        float v = g_upd[(size_t)a * D_ATOM + j];
        s += v; q += v * v;
    }
    atomicAdd(&g_stats2[j], s);
    atomicAdd(&g_stats2[D_ATOM + j], q);
}

__global__ void finalize2_kernel(const float* __restrict__ gamma,
                                 const float* __restrict__ beta, int N) {
    int j = threadIdx.x;
    float inv_n = 1.f / (float)N;
    float mean = g_stats2[j] * inv_n;
    float var = g_stats2[D_ATOM + j] * inv_n - mean * mean;
    float sc = rsqrtf(var + 1e-5f) * gamma[j];
    g_scale2[j] = sc;
    g_shift2[j] = beta[j] - mean * sc;
}

// ---- 6: out = softplus(atom_in + BN2(update)) ----
__global__ void out_kernel(const float* __restrict__ atom, float* __restrict__ out, int N) {
    int idx = blockIdx.x * blockDim.x + threadIdx.x;
    if (idx >= N * D_ATOM) return;
    int j = idx & (D_ATOM - 1);
    float u = g_upd[idx] * g_scale2[j] + g_shift2[j];
    float x = atom[idx] + u;
    out[idx] = fmaxf(x, 0.f) + log1pf(expf(-fabsf(x)));
}

extern "C" void kernel_launch(void* const* d_in, const int* in_sizes, int n_in,
                              void* d_out, int out_size) {
    const float* atom = (const float*)d_in[0];
    const float* nbr  = (const float*)d_in[1];
    const int* esrc   = (const int*)d_in[2];
    const int* edst   = (const int*)d_in[3];
    const float* W    = (const float*)d_in[4];
    const float* b    = (const float*)d_in[5];
    const float* g1   = (const float*)d_in[6];
    const float* b1   = (const float*)d_in[7];
    const float* g2   = (const float*)d_in[8];
    const float* b2   = (const float*)d_in[9];
    float* out = (float*)d_out;

    int N = in_sizes[0] / D_ATOM;
    int E = in_sizes[2];

    cudaFuncSetAttribute(pgemm_kernel, cudaFuncAttributeMaxDynamicSharedMemorySize, PG_SMEM);
    cudaFuncSetAttribute(egemm_kernel, cudaFuncAttributeMaxDynamicSharedMemorySize, EG_SMEM);

    wprep_kernel<<<(128 * 64 + 255) / 256, 256>>>(W);
    init_kernel<<<(N * D_ATOM + 255) / 256, 256>>>(N * D_ATOM);
    dim3 pg((N + 127) / 128, 2);
    pgemm_kernel<<<pg, 256, PG_SMEM>>>(atom, W, N);
    egemm_kernel<<<(E + 127) / 128, 256, EG_SMEM>>>(nbr, esrc, edst, b, E);
    finalize1_kernel<<<1, DOUT>>>(g1, b1, E);
    long long msg_work = (long long)E * 8;
    msg_kernel<<<(unsigned)((msg_work + 255) / 256), 256>>>(edst, E);
    bn2_stats_kernel<<<256, 256>>>(N);
    finalize2_kernel<<<1, D_ATOM>>>(g2, b2, N);
    out_kernel<<<(N * D_ATOM + 255) / 256, 256>>>(atom, out, N);
}